// round 16
// baseline (speedup 1.0000x reference)
#include <cuda_runtime.h>
#include <cuda_bf16.h>
#include <cstdint>

// out = (((x+2)*3-5)/4)^2 = ((3x+1)/4)^2 ; t = fma(0.75, x, 0.25), out = t*t
// 64M fp32, pure HBM streaming, pinned at the GB300 controller ceiling
// (~6.4-6.5 TB/s measured, 80-81% of spec; invariant across unroll 2/4/8,
// 256/512-thread CTAs, cache hints; persistent grid-stride regresses).
// Best-measured config (R7): exact-size unroll-8, 256 threads, front-batched
// .cg loads, .cs stores, one-shot 8192-block grid.

__global__ __launch_bounds__(256) void ewise_sq8_kernel(
    const float4* __restrict__ in, float4* __restrict__ out)
{
    const unsigned base = blockIdx.x * (256u * 8u) + threadIdx.x;
    const unsigned s = 256u;

    // Front-batch all 8 loads -> 8 outstanding LDG.128 per thread.
    float4 a0 = __ldcg(&in[base]);
    float4 a1 = __ldcg(&in[base + s]);
    float4 a2 = __ldcg(&in[base + 2u * s]);
    float4 a3 = __ldcg(&in[base + 3u * s]);
    float4 a4 = __ldcg(&in[base + 4u * s]);
    float4 a5 = __ldcg(&in[base + 5u * s]);
    float4 a6 = __ldcg(&in[base + 6u * s]);
    float4 a7 = __ldcg(&in[base + 7u * s]);

    #define EW(dst, src) do {                       \
        float t0 = fmaf(0.75f, (src).x, 0.25f);     \
        float t1 = fmaf(0.75f, (src).y, 0.25f);     \
        float t2 = fmaf(0.75f, (src).z, 0.25f);     \
        float t3 = fmaf(0.75f, (src).w, 0.25f);     \
        (dst).x = t0 * t0; (dst).y = t1 * t1;       \
        (dst).z = t2 * t2; (dst).w = t3 * t3;       \
    } while (0)

    float4 r0, r1, r2, r3, r4, r5, r6, r7;
    EW(r0, a0); EW(r1, a1); EW(r2, a2); EW(r3, a3);
    EW(r4, a4); EW(r5, a5); EW(r6, a6); EW(r7, a7);
    #undef EW

    __stcs(&out[base],          r0);
    __stcs(&out[base + s],      r1);
    __stcs(&out[base + 2u * s], r2);
    __stcs(&out[base + 3u * s], r3);
    __stcs(&out[base + 4u * s], r4);
    __stcs(&out[base + 5u * s], r5);
    __stcs(&out[base + 6u * s], r6);
    __stcs(&out[base + 7u * s], r7);
}

// Vector tail for full float4s beyond the exact-size region.
__global__ void ewise_sq_vec_tail(const float4* __restrict__ in,
                                  float4* __restrict__ out,
                                  unsigned start4, unsigned n4)
{
    unsigned i = start4 + blockIdx.x * blockDim.x + threadIdx.x;
    if (i < n4) {
        float4 a = __ldcg(&in[i]);
        float4 r;
        float t0 = fmaf(0.75f, a.x, 0.25f);
        float t1 = fmaf(0.75f, a.y, 0.25f);
        float t2 = fmaf(0.75f, a.z, 0.25f);
        float t3 = fmaf(0.75f, a.w, 0.25f);
        r.x = t0 * t0; r.y = t1 * t1; r.z = t2 * t2; r.w = t3 * t3;
        __stcs(&out[i], r);
    }
}

// Scalar tail for element counts not divisible by 4.
__global__ void ewise_sq_scalar_tail(const float* __restrict__ in,
                                     float* __restrict__ out,
                                     unsigned start, unsigned n)
{
    unsigned i = start + blockIdx.x * blockDim.x + threadIdx.x;
    if (i < n) {
        float t = fmaf(0.75f, in[i], 0.25f);
        out[i] = t * t;
    }
}

extern "C" void kernel_launch(void* const* d_in, const int* in_sizes, int n_in,
                              void* d_out, int out_size)
{
    const float* x = (const float*)d_in[0];
    float* y = (float*)d_out;
    unsigned n = (unsigned)in_sizes[0];   // 67108864 for this problem
    unsigned n4 = n >> 2;                 // 16777216 float4

    const unsigned per_block4 = 256u * 8u;        // 2048 float4 per block
    unsigned full_blocks = n4 / per_block4;       // 8192 blocks (exact here)
    unsigned covered4 = full_blocks * per_block4;

    if (full_blocks > 0) {
        ewise_sq8_kernel<<<full_blocks, 256>>>((const float4*)x, (float4*)y);
    }
    if (covered4 < n4) {
        unsigned rem4 = n4 - covered4;
        unsigned tb = (rem4 + 255u) / 256u;
        ewise_sq_vec_tail<<<tb, 256>>>((const float4*)x, (float4*)y, covered4, n4);
    }
    unsigned covered = n4 << 2;
    if (covered < n) {
        unsigned rem = n - covered;
        unsigned tb = (rem + 255u) / 256u;
        ewise_sq_scalar_tail<<<tb, 256>>>(x, y, covered, n);
    }
}